// round 1
// baseline (speedup 1.0000x reference)
#include <cuda_runtime.h>
#include <cstddef>

#define DIM     512
#define BATCH   8
#define SEQ     4096
#define M_TOTAL (BATCH * SEQ)   // 32768

// Scratch (allocation-free rule: __device__ globals)
__device__ float g_q[(size_t)M_TOTAL * DIM];   // 64 MB
__device__ float g_k[(size_t)M_TOTAL * DIM];   // 64 MB
__device__ float g_u[(size_t)M_TOTAL * DIM];   // 64 MB
__device__ float g_gq[BATCH * DIM];

// ---------------------------------------------------------------------------
// SGEMM: C[M,N] = op(A)[M,K] @ W[K,N] + bias[N] (+ addend[M,N] if MODE==2)
// MODE 0: op(A) = A
// MODE 2: op(A)[m,kk] = A[m,kk] * gq[batch(m)*DIM + kk]   (gq broadcast over rows)
// BM=BN=128, BK=16, 256 threads, 8x8 per thread.
// M % 128 == 0, N % 128 == 0, K % 16 == 0 assumed (true here).
// ---------------------------------------------------------------------------
template <int MODE>
__global__ __launch_bounds__(256, 2)
void sgemm_kernel(const float* __restrict__ A,
                  const float* __restrict__ W,
                  const float* __restrict__ bias,
                  const float* __restrict__ addend,
                  const float* __restrict__ gq,
                  float* __restrict__ C,
                  int M, int N, int K)
{
    constexpr int BM = 128, BN = 128, BK = 16;
    __shared__ float As[BK][BM];
    __shared__ float Bs[BK][BN];

    const int tid  = threadIdx.x;
    const int row0 = blockIdx.y * BM;
    const int col0 = blockIdx.x * BN;
    const int tx = tid & 15;       // 0..15  -> column micro-tile
    const int ty = tid >> 4;       // 0..15  -> row micro-tile

    // A tile loading: 4 threads per row (float4 over 16 cols), 64 rows/pass, 2 passes
    const int arow = tid >> 2;           // 0..63
    const int acol = (tid & 3) * 4;      // 0,4,8,12
    // B tile loading: 32 threads per row (float4 over 128 cols), 8 rows/pass, 2 passes
    const int brow = tid >> 5;           // 0..7
    const int bcol = (tid & 31) * 4;

    const int bb = (MODE == 2) ? (row0 / SEQ) : 0;   // batch of this M tile

    float acc[8][8];
#pragma unroll
    for (int i = 0; i < 8; i++)
#pragma unroll
        for (int j = 0; j < 8; j++) acc[i][j] = 0.0f;

    const float* Abase = A + (size_t)row0 * K;

    for (int k0 = 0; k0 < K; k0 += BK) {
        // ---- load A tile (optionally scaled by gq along K) ----
        float4 gscale;
        if (MODE == 2)
            gscale = *reinterpret_cast<const float4*>(gq + bb * DIM + k0 + acol);
#pragma unroll
        for (int p = 0; p < 2; p++) {
            int r = arow + p * 64;
            float4 v = *reinterpret_cast<const float4*>(Abase + (size_t)r * K + k0 + acol);
            if (MODE == 2) {
                v.x *= gscale.x; v.y *= gscale.y; v.z *= gscale.z; v.w *= gscale.w;
            }
            As[acol + 0][r] = v.x;
            As[acol + 1][r] = v.y;
            As[acol + 2][r] = v.z;
            As[acol + 3][r] = v.w;
        }
        // ---- load B tile ----
#pragma unroll
        for (int p = 0; p < 2; p++) {
            int r = brow + p * 8;
            float4 v = *reinterpret_cast<const float4*>(W + (size_t)(k0 + r) * N + col0 + bcol);
            *reinterpret_cast<float4*>(&Bs[r][bcol]) = v;
        }
        __syncthreads();

        // ---- compute ----
#pragma unroll
        for (int kk = 0; kk < BK; kk++) {
            float a[8], b[8];
            *reinterpret_cast<float4*>(&a[0]) = *reinterpret_cast<float4*>(&As[kk][ty * 8]);
            *reinterpret_cast<float4*>(&a[4]) = *reinterpret_cast<float4*>(&As[kk][ty * 8 + 4]);
            *reinterpret_cast<float4*>(&b[0]) = *reinterpret_cast<float4*>(&Bs[kk][tx * 8]);
            *reinterpret_cast<float4*>(&b[4]) = *reinterpret_cast<float4*>(&Bs[kk][tx * 8 + 4]);
#pragma unroll
            for (int i = 0; i < 8; i++)
#pragma unroll
                for (int j = 0; j < 8; j++)
                    acc[i][j] = fmaf(a[i], b[j], acc[i][j]);
        }
        __syncthreads();
    }

    // ---- epilogue ----
    float4 b4lo = *reinterpret_cast<const float4*>(bias + col0 + tx * 8);
    float4 b4hi = *reinterpret_cast<const float4*>(bias + col0 + tx * 8 + 4);
#pragma unroll
    for (int i = 0; i < 8; i++) {
        int r = row0 + ty * 8 + i;
        float4 lo, hi;
        lo.x = acc[i][0] + b4lo.x; lo.y = acc[i][1] + b4lo.y;
        lo.z = acc[i][2] + b4lo.z; lo.w = acc[i][3] + b4lo.w;
        hi.x = acc[i][4] + b4hi.x; hi.y = acc[i][5] + b4hi.y;
        hi.z = acc[i][6] + b4hi.z; hi.w = acc[i][7] + b4hi.w;
        if (MODE == 2) {
            const float* ad = addend + (size_t)r * N + col0 + tx * 8;
            float4 alo = *reinterpret_cast<const float4*>(ad);
            float4 ahi = *reinterpret_cast<const float4*>(ad + 4);
            lo.x += alo.x; lo.y += alo.y; lo.z += alo.z; lo.w += alo.w;
            hi.x += ahi.x; hi.y += ahi.y; hi.z += ahi.z; hi.w += ahi.w;
        }
        float* cp = C + (size_t)r * N + col0 + tx * 8;
        *reinterpret_cast<float4*>(cp)     = lo;
        *reinterpret_cast<float4*>(cp + 4) = hi;
    }
}

// ---------------------------------------------------------------------------
// Row-wise L2 normalize q and k in place. grid = M_TOTAL, 128 threads.
// ---------------------------------------------------------------------------
__global__ void l2norm_kernel(float* __restrict__ q, float* __restrict__ k)
{
    const int row = blockIdx.x;
    const int tid = threadIdx.x;                     // 0..127, 4 floats each
    float4* qr = reinterpret_cast<float4*>(q + (size_t)row * DIM);
    float4* kr = reinterpret_cast<float4*>(k + (size_t)row * DIM);

    float4 qv = qr[tid];
    float4 kv = kr[tid];
    float sq = qv.x * qv.x + qv.y * qv.y + qv.z * qv.z + qv.w * qv.w;
    float sk = kv.x * kv.x + kv.y * kv.y + kv.z * kv.z + kv.w * kv.w;

#pragma unroll
    for (int o = 16; o > 0; o >>= 1) {
        sq += __shfl_xor_sync(0xFFFFFFFFu, sq, o);
        sk += __shfl_xor_sync(0xFFFFFFFFu, sk, o);
    }
    __shared__ float sh[8];
    const int wid = tid >> 5, lane = tid & 31;
    if (lane == 0) { sh[wid] = sq; sh[4 + wid] = sk; }
    __syncthreads();
    sq = sh[0] + sh[1] + sh[2] + sh[3];
    sk = sh[4] + sh[5] + sh[6] + sh[7];

    const float rq = rsqrtf(fmaxf(sq, 1e-12f));
    const float rk = rsqrtf(fmaxf(sk, 1e-12f));

    qv.x *= rq; qv.y *= rq; qv.z *= rq; qv.w *= rq;
    kv.x *= rk; kv.y *= rk; kv.z *= rk; kv.w *= rk;
    qr[tid] = qv;
    kr[tid] = kv;
}

__global__ void zero_gq_kernel(float* __restrict__ gq)
{
    int i = blockIdx.x * blockDim.x + threadIdx.x;
    if (i < BATCH * DIM) gq[i] = 0.0f;
}

// gq[b,d] = sum_n qn[b,n,d].  grid = (DIM/128, BATCH, SEQ/256), 128 threads.
__global__ void batch_sum_kernel(const float* __restrict__ qn, float* __restrict__ gq)
{
    const int d  = blockIdx.x * 128 + threadIdx.x;
    const int b  = blockIdx.y;
    const int n0 = blockIdx.z * 256;
    const float* base = qn + ((size_t)b * SEQ + n0) * DIM + d;
    float s = 0.0f;
#pragma unroll 8
    for (int i = 0; i < 256; i++) s += base[(size_t)i * DIM];
    atomicAdd(&gq[b * DIM + d], s);
}

// ---------------------------------------------------------------------------
extern "C" void kernel_launch(void* const* d_in, const int* in_sizes, int n_in,
                              void* d_out, int out_size)
{
    const float* x  = (const float*)d_in[0];
    const float* wq = (const float*)d_in[1];
    const float* bq = (const float*)d_in[2];
    const float* wk = (const float*)d_in[3];
    const float* bk = (const float*)d_in[4];
    const float* wp = (const float*)d_in[5];
    const float* bp = (const float*)d_in[6];
    const float* wf = (const float*)d_in[7];
    const float* bf = (const float*)d_in[8];
    // d_in[9] = w_g: softmax over a size-1 axis is identically 1 -> w_g unused.
    float* out = (float*)d_out;

    float *q, *k, *u, *gq;
    cudaGetSymbolAddress((void**)&q,  g_q);
    cudaGetSymbolAddress((void**)&k,  g_k);
    cudaGetSymbolAddress((void**)&u,  g_u);
    cudaGetSymbolAddress((void**)&gq, g_gq);

    dim3 gg(DIM / 128, M_TOTAL / 128);
    dim3 tt(256);

    // q = x@wq + bq ; k = x@wk + bk
    sgemm_kernel<0><<<gg, tt>>>(x, wq, bq, nullptr, nullptr, q, M_TOTAL, DIM, DIM);
    sgemm_kernel<0><<<gg, tt>>>(x, wk, bk, nullptr, nullptr, k, M_TOTAL, DIM, DIM);

    // L2-normalize rows of q, k (in place)
    l2norm_kernel<<<M_TOTAL, 128>>>(q, k);

    // gq[b] = sum_n q_norm[b,n,:]   (softmax over size-1 axis == 1)
    zero_gq_kernel<<<(BATCH * DIM + 255) / 256, 256>>>(gq);
    batch_sum_kernel<<<dim3(DIM / 128, BATCH, SEQ / 256), 128>>>(q, gq);

    // u = (gq ⊙ k) @ wp + bp + q
    sgemm_kernel<2><<<gg, tt>>>(k, wp, bp, q, gq, u, M_TOTAL, DIM, DIM);

    // out = u @ wf + bf
    sgemm_kernel<0><<<gg, tt>>>(u, wf, bf, nullptr, nullptr, out, M_TOTAL, DIM, DIM);
}

// round 4
// speedup vs baseline: 2.1069x; 2.1069x over previous
#include <cuda_runtime.h>
#include <cuda_bf16.h>
#include <cstdint>
#include <cstddef>

#define DIM     512
#define BATCH   8
#define SEQ     4096
#define M_TOTAL (BATCH * SEQ)   // 32768

// ---------------------------------------------------------------------------
// Scratch (__device__ globals; no allocation allowed)
// ---------------------------------------------------------------------------
__device__ __nv_bfloat16 g_ah[(size_t)M_TOTAL * DIM];   // x hi  -> later u hi
__device__ __nv_bfloat16 g_al[(size_t)M_TOTAL * DIM];   // x lo  -> later u lo
__device__ float         g_q [(size_t)M_TOTAL * DIM];   // q -> qn (in place)
__device__ float         g_k [(size_t)M_TOTAL * DIM];   // k (pre-norm)
__device__ __nv_bfloat16 g_knh[(size_t)M_TOTAL * DIM];  // k normalized hi
__device__ __nv_bfloat16 g_knl[(size_t)M_TOTAL * DIM];  // k normalized lo
__device__ __nv_bfloat16 g_wTh[3u * DIM * DIM];         // wq^T, wk^T, wf^T hi (concat rows)
__device__ __nv_bfloat16 g_wTl[3u * DIM * DIM];         // lo
__device__ __nv_bfloat16 g_wpTh[(size_t)BATCH * DIM * DIM]; // (diag(gq_b) wp)^T hi
__device__ __nv_bfloat16 g_wpTl[(size_t)BATCH * DIM * DIM]; // lo
__device__ float         g_gq[BATCH * DIM];

// ---------------------------------------------------------------------------
// helpers
// ---------------------------------------------------------------------------
__device__ __forceinline__ uint32_t smem_u32(const void* p) {
    uint32_t a;
    asm("{ .reg .u64 t; cvta.to.shared.u64 t, %1; cvt.u32.u64 %0, t; }" : "=r"(a) : "l"(p));
    return a;
}
__device__ __forceinline__ uint32_t swz(uint32_t o) { return o ^ ((o >> 3) & 0x70); }

__device__ __forceinline__ void cp16(uint32_t s, const void* g) {
    asm volatile("cp.async.cg.shared.global [%0], [%1], 16;\n" :: "r"(s), "l"(g));
}
#define CP_COMMIT() asm volatile("cp.async.commit_group;\n" ::: "memory")
#define CP_WAIT1()  asm volatile("cp.async.wait_group 1;\n" ::: "memory")

__device__ __forceinline__ void ldsm4(uint32_t* r, uint32_t addr) {
    asm volatile("ldmatrix.sync.aligned.m8n8.x4.shared.b16 {%0,%1,%2,%3}, [%4];\n"
                 : "=r"(r[0]), "=r"(r[1]), "=r"(r[2]), "=r"(r[3]) : "r"(addr));
}
__device__ __forceinline__ void mma16816(float* d, const uint32_t* a, const uint32_t* b) {
    asm volatile(
        "mma.sync.aligned.m16n8k16.row.col.f32.bf16.bf16.f32 "
        "{%0,%1,%2,%3}, {%4,%5,%6,%7}, {%8,%9}, {%0,%1,%2,%3};\n"
        : "+f"(d[0]), "+f"(d[1]), "+f"(d[2]), "+f"(d[3])
        : "r"(a[0]), "r"(a[1]), "r"(a[2]), "r"(a[3]), "r"(b[0]), "r"(b[1]));
}

__device__ __forceinline__ void split1(float v, __nv_bfloat16& h, __nv_bfloat16& l) {
    h = __float2bfloat16(v);
    l = __float2bfloat16(v - __bfloat162float(h));
}

// ---------------------------------------------------------------------------
// bf16-split GEMM:  C[M,N] = (Ah+Al)[M,512] @ (Bh+Bl)[N,512]^T (+bias)(+addend)
// Logical K' = 1536 = 24 chunks of 64:
//   chunks 0..7  : Ah x Bh    8..15 : Al x Bh    16..23 : Ah x Bl
// CTA 128x128, 8 warps (2M x 4N of 64x32 warp tiles), 3-stage cp.async.
// MODE 0: two fp32 outputs (cols <512 -> out0/bias0, >=512 -> out1/bias1)
// MODE 1: per-batch B, fp32 addend added, result split to (outH, outL) bf16
// MODE 2: single fp32 output + bias0
// ---------------------------------------------------------------------------
#define STAGES 3
#define CHUNKS 24
#define GEMM_SMEM (STAGES * 32768)   // 96 KB

__device__ __forceinline__ void load_chunk(
    const __nv_bfloat16* __restrict__ Ah, const __nv_bfloat16* __restrict__ Al,
    const __nv_bfloat16* __restrict__ Bh, const __nv_bfloat16* __restrict__ Bl,
    int m0, int n0, int c, uint32_t sA, uint32_t sB, int t)
{
    const __nv_bfloat16* Ap = (c < 8 || c >= 16) ? Ah : Al;
    const __nv_bfloat16* Bp = (c < 16) ? Bh : Bl;
    const int k0 = (c & 7) * 64;
    const int ch = t & 7;          // 16B chunk within 128B row
    const int rb = t >> 3;         // 0..31
#pragma unroll
    for (int it = 0; it < 4; it++) {
        int r = it * 32 + rb;
        cp16(sA + swz((uint32_t)(r * 128 + ch * 16)),
             Ap + (size_t)(m0 + r) * DIM + k0 + ch * 8);
    }
#pragma unroll
    for (int it = 0; it < 4; it++) {
        int r = it * 32 + rb;
        cp16(sB + swz((uint32_t)(r * 128 + ch * 16)),
             Bp + (size_t)(n0 + r) * DIM + k0 + ch * 8);
    }
}

template <int MODE>
__global__ __launch_bounds__(256, 1)
void mma_gemm(const __nv_bfloat16* __restrict__ Ah, const __nv_bfloat16* __restrict__ Al,
              const __nv_bfloat16* __restrict__ Bh, const __nv_bfloat16* __restrict__ Bl,
              const float* __restrict__ bias0, const float* __restrict__ bias1,
              const float* __restrict__ addend,
              float* __restrict__ out0, float* __restrict__ out1,
              __nv_bfloat16* __restrict__ outH, __nv_bfloat16* __restrict__ outL)
{
    extern __shared__ char smem[];
    const uint32_t sb = smem_u32(smem);
    const int t = threadIdx.x;
    const int w = t >> 5, l = t & 31;
    const int m0 = blockIdx.y * 128;
    const int n0 = blockIdx.x * 128;

    if (MODE == 1) {
        size_t bo = (size_t)(m0 / SEQ) * DIM * DIM;
        Bh += bo; Bl += bo;
    }

    uint32_t sA[STAGES], sB[STAGES];
#pragma unroll
    for (int s = 0; s < STAGES; s++) { sA[s] = sb + s * 32768u; sB[s] = sA[s] + 16384u; }

    // prologue: chunks 0,1
    load_chunk(Ah, Al, Bh, Bl, m0, n0, 0, sA[0], sB[0], t); CP_COMMIT();
    load_chunk(Ah, Al, Bh, Bl, m0, n0, 1, sA[1], sB[1], t); CP_COMMIT();

    const int wm = w & 1;          // M half (0/1) -> 64 rows
    const int wn = w >> 1;         // N quarter (0..3) -> 32 cols
    const uint32_t aBase = (uint32_t)((wm * 64 + (l & 15)) * 128 + (l >> 4) * 16);
    const uint32_t bBase = (uint32_t)((wn * 32 + ((l >> 4) * 8) + (l & 7)) * 128
                                      + ((l >> 3) & 1) * 16);

    float acc[4][4][4];
#pragma unroll
    for (int i = 0; i < 4; i++)
#pragma unroll
        for (int j = 0; j < 4; j++)
#pragma unroll
            for (int e = 0; e < 4; e++) acc[i][j][e] = 0.0f;

    for (int c = 0; c < CHUNKS; c++) {
        CP_WAIT1();
        __syncthreads();
        const int pf = c + 2;
        if (pf < CHUNKS)
            load_chunk(Ah, Al, Bh, Bl, m0, n0, pf, sA[pf % 3], sB[pf % 3], t);
        CP_COMMIT();

        const uint32_t cA = sA[c % 3], cB = sB[c % 3];
#pragma unroll
        for (int s = 0; s < 4; s++) {
            uint32_t a[4][4], b[4][2];
#pragma unroll
            for (int i = 0; i < 4; i++) {
                uint32_t off = aBase + i * 2048 + s * 32;
                ldsm4(a[i], cA + (off ^ ((off >> 3) & 0x70)));
            }
#pragma unroll
            for (int jj = 0; jj < 2; jj++) {
                uint32_t off = bBase + jj * 2048 + s * 32;
                uint32_t r[4];
                ldsm4(r, cB + (off ^ ((off >> 3) & 0x70)));
                b[2 * jj][0] = r[0]; b[2 * jj][1] = r[1];
                b[2 * jj + 1][0] = r[2]; b[2 * jj + 1][1] = r[3];
            }
#pragma unroll
            for (int i = 0; i < 4; i++)
#pragma unroll
                for (int j = 0; j < 4; j++)
                    mma16816(acc[i][j], a[i], b[j]);
        }
    }

    // ---- epilogue ----
    const float* bias = bias0;
    float* outp = out0;
    int cb = n0;
    if (MODE == 0 && n0 >= 512) { bias = bias1; outp = out1; cb = n0 - 512; }

    const int colw = cb + wn * 32 + (l & 3) * 2;
    float bj[4][2];
#pragma unroll
    for (int j = 0; j < 4; j++) {
        bj[j][0] = bias[colw + j * 8];
        bj[j][1] = bias[colw + j * 8 + 1];
    }

    const int mrow = m0 + wm * 64 + (l >> 2);
#pragma unroll
    for (int i = 0; i < 4; i++) {
        int r0 = mrow + i * 16, r1 = r0 + 8;
#pragma unroll
        for (int j = 0; j < 4; j++) {
            int cc = colw + j * 8;
            float v0 = acc[i][j][0] + bj[j][0];
            float v1 = acc[i][j][1] + bj[j][1];
            float v2 = acc[i][j][2] + bj[j][0];
            float v3 = acc[i][j][3] + bj[j][1];
            size_t o0 = (size_t)r0 * DIM + cc;
            size_t o1 = (size_t)r1 * DIM + cc;
            if (MODE == 1) {
                float2 a0 = *reinterpret_cast<const float2*>(addend + o0);
                float2 a1 = *reinterpret_cast<const float2*>(addend + o1);
                v0 += a0.x; v1 += a0.y; v2 += a1.x; v3 += a1.y;
                __nv_bfloat16 h0, h1, h2, h3, l0, l1, l2, l3;
                split1(v0, h0, l0); split1(v1, h1, l1);
                split1(v2, h2, l2); split1(v3, h3, l3);
                *reinterpret_cast<__nv_bfloat162*>(outH + o0) = __nv_bfloat162(h0, h1);
                *reinterpret_cast<__nv_bfloat162*>(outH + o1) = __nv_bfloat162(h2, h3);
                *reinterpret_cast<__nv_bfloat162*>(outL + o0) = __nv_bfloat162(l0, l1);
                *reinterpret_cast<__nv_bfloat162*>(outL + o1) = __nv_bfloat162(l2, l3);
            } else {
                *reinterpret_cast<float2*>(outp + o0) = make_float2(v0, v1);
                *reinterpret_cast<float2*>(outp + o1) = make_float2(v2, v3);
            }
        }
    }
}

// ---------------------------------------------------------------------------
// x -> bf16 hi/lo split
// ---------------------------------------------------------------------------
__global__ void split_x_kernel(const float* __restrict__ x,
                               __nv_bfloat16* __restrict__ h,
                               __nv_bfloat16* __restrict__ l)
{
    size_t i = (size_t)blockIdx.x * blockDim.x + threadIdx.x;   // float4 index
    float4 v = reinterpret_cast<const float4*>(x)[i];
    __nv_bfloat16 h0, h1, h2, h3, l0, l1, l2, l3;
    split1(v.x, h0, l0); split1(v.y, h1, l1); split1(v.z, h2, l2); split1(v.w, h3, l3);
    reinterpret_cast<__nv_bfloat162*>(h)[2 * i]     = __nv_bfloat162(h0, h1);
    reinterpret_cast<__nv_bfloat162*>(h)[2 * i + 1] = __nv_bfloat162(h2, h3);
    reinterpret_cast<__nv_bfloat162*>(l)[2 * i]     = __nv_bfloat162(l0, l1);
    reinterpret_cast<__nv_bfloat162*>(l)[2 * i + 1] = __nv_bfloat162(l2, l3);
}

// ---------------------------------------------------------------------------
// Transpose + split the three static weights: out[z][n][k] = split(w_z[k][n])
// ---------------------------------------------------------------------------
__global__ void wsplit_kernel(const float* __restrict__ wq,
                              const float* __restrict__ wk,
                              const float* __restrict__ wf,
                              __nv_bfloat16* __restrict__ th,
                              __nv_bfloat16* __restrict__ tl)
{
    __shared__ float sm[32][33];
    const int z = blockIdx.z;
    const float* w = (z == 0) ? wq : (z == 1) ? wk : wf;
    const int n0 = blockIdx.x * 32, k0 = blockIdx.y * 32;
    sm[threadIdx.y][threadIdx.x] = w[(size_t)(k0 + threadIdx.y) * DIM + n0 + threadIdx.x];
    __syncthreads();
    float v = sm[threadIdx.x][threadIdx.y];   // w[k0+tx][n0+ty]
    size_t o = (size_t)z * DIM * DIM + (size_t)(n0 + threadIdx.y) * DIM + k0 + threadIdx.x;
    __nv_bfloat16 h, l; split1(v, h, l);
    th[o] = h; tl[o] = l;
}

// out[b][n][k] = split(gq[b][k] * wp[k][n])
__global__ void wpsplit_kernel(const float* __restrict__ wp,
                               const float* __restrict__ gq,
                               __nv_bfloat16* __restrict__ th,
                               __nv_bfloat16* __restrict__ tl)
{
    __shared__ float sm[32][33];
    const int b = blockIdx.z;
    const int n0 = blockIdx.x * 32, k0 = blockIdx.y * 32;
    sm[threadIdx.y][threadIdx.x] = wp[(size_t)(k0 + threadIdx.y) * DIM + n0 + threadIdx.x];
    __syncthreads();
    float v = sm[threadIdx.x][threadIdx.y] * gq[b * DIM + k0 + threadIdx.x];
    size_t o = (size_t)b * DIM * DIM + (size_t)(n0 + threadIdx.y) * DIM + k0 + threadIdx.x;
    __nv_bfloat16 h, l; split1(v, h, l);
    th[o] = h; tl[o] = l;
}

// ---------------------------------------------------------------------------
// L2-normalize q (in place, fp32) and k (-> bf16 split). grid = M_TOTAL, 128 thr.
// ---------------------------------------------------------------------------
__global__ void l2norm_kernel(float* __restrict__ q, const float* __restrict__ k,
                              __nv_bfloat16* __restrict__ knh,
                              __nv_bfloat16* __restrict__ knl)
{
    const int row = blockIdx.x;
    const int tid = threadIdx.x;
    float4* qr = reinterpret_cast<float4*>(q + (size_t)row * DIM);
    const float4* kr = reinterpret_cast<const float4*>(k + (size_t)row * DIM);

    float4 qv = qr[tid];
    float4 kv = kr[tid];
    float sq = qv.x * qv.x + qv.y * qv.y + qv.z * qv.z + qv.w * qv.w;
    float sk = kv.x * kv.x + kv.y * kv.y + kv.z * kv.z + kv.w * kv.w;
#pragma unroll
    for (int o = 16; o > 0; o >>= 1) {
        sq += __shfl_xor_sync(0xFFFFFFFFu, sq, o);
        sk += __shfl_xor_sync(0xFFFFFFFFu, sk, o);
    }
    __shared__ float sh[8];
    const int wid = tid >> 5, lane = tid & 31;
    if (lane == 0) { sh[wid] = sq; sh[4 + wid] = sk; }
    __syncthreads();
    sq = sh[0] + sh[1] + sh[2] + sh[3];
    sk = sh[4] + sh[5] + sh[6] + sh[7];
    const float rq = rsqrtf(fmaxf(sq, 1e-12f));
    const float rk = rsqrtf(fmaxf(sk, 1e-12f));

    qv.x *= rq; qv.y *= rq; qv.z *= rq; qv.w *= rq;
    qr[tid] = qv;

    kv.x *= rk; kv.y *= rk; kv.z *= rk; kv.w *= rk;
    __nv_bfloat16 h0, h1, h2, h3, l0, l1, l2, l3;
    split1(kv.x, h0, l0); split1(kv.y, h1, l1); split1(kv.z, h2, l2); split1(kv.w, h3, l3);
    size_t o = (size_t)row * (DIM / 2) + tid * 2;
    reinterpret_cast<__nv_bfloat162*>(knh)[o]     = __nv_bfloat162(h0, h1);
    reinterpret_cast<__nv_bfloat162*>(knh)[o + 1] = __nv_bfloat162(h2, h3);
    reinterpret_cast<__nv_bfloat162*>(knl)[o]     = __nv_bfloat162(l0, l1);
    reinterpret_cast<__nv_bfloat162*>(knl)[o + 1] = __nv_bfloat162(l2, l3);
}

__global__ void zero_gq_kernel(float* __restrict__ gq)
{
    int i = blockIdx.x * blockDim.x + threadIdx.x;
    if (i < BATCH * DIM) gq[i] = 0.0f;
}

// gq[b,d] = sum_n qn[b,n,d]
__global__ void batch_sum_kernel(const float* __restrict__ qn, float* __restrict__ gq)
{
    const int d  = blockIdx.x * 128 + threadIdx.x;
    const int b  = blockIdx.y;
    const int n0 = blockIdx.z * 256;
    const float* base = qn + ((size_t)b * SEQ + n0) * DIM + d;
    float s = 0.0f;
#pragma unroll 8
    for (int i = 0; i < 256; i++) s += base[(size_t)i * DIM];
    atomicAdd(&gq[b * DIM + d], s);
}

// ---------------------------------------------------------------------------
extern "C" void kernel_launch(void* const* d_in, const int* in_sizes, int n_in,
                              void* d_out, int out_size)
{
    const float* x  = (const float*)d_in[0];
    const float* wq = (const float*)d_in[1];
    const float* bq = (const float*)d_in[2];
    const float* wk = (const float*)d_in[3];
    const float* bk = (const float*)d_in[4];
    const float* wp = (const float*)d_in[5];
    const float* bp = (const float*)d_in[6];
    const float* wf = (const float*)d_in[7];
    const float* bf = (const float*)d_in[8];
    // d_in[9] = w_g: softmax over size-1 axis == 1 -> unused
    float* out = (float*)d_out;

    __nv_bfloat16 *ah, *al, *knh, *knl, *wTh, *wTl, *wpTh, *wpTl;
    float *q, *k, *gq;
    cudaGetSymbolAddress((void**)&ah,  g_ah);
    cudaGetSymbolAddress((void**)&al,  g_al);
    cudaGetSymbolAddress((void**)&q,   g_q);
    cudaGetSymbolAddress((void**)&k,   g_k);
    cudaGetSymbolAddress((void**)&knh, g_knh);
    cudaGetSymbolAddress((void**)&knl, g_knl);
    cudaGetSymbolAddress((void**)&wTh, g_wTh);
    cudaGetSymbolAddress((void**)&wTl, g_wTl);
    cudaGetSymbolAddress((void**)&wpTh, g_wpTh);
    cudaGetSymbolAddress((void**)&wpTl, g_wpTl);
    cudaGetSymbolAddress((void**)&gq,  g_gq);

    cudaFuncSetAttribute(mma_gemm<0>, cudaFuncAttributeMaxDynamicSharedMemorySize, GEMM_SMEM);
    cudaFuncSetAttribute(mma_gemm<1>, cudaFuncAttributeMaxDynamicSharedMemorySize, GEMM_SMEM);
    cudaFuncSetAttribute(mma_gemm<2>, cudaFuncAttributeMaxDynamicSharedMemorySize, GEMM_SMEM);

    const int MT = M_TOTAL / 128;   // 256 row tiles

    // split x into bf16 hi/lo
    split_x_kernel<<<(size_t)M_TOTAL * DIM / 4 / 256, 256>>>(x, ah, al);
    // transpose + split static weights (wq^T | wk^T | wf^T concatenated)
    wsplit_kernel<<<dim3(16, 16, 3), dim3(32, 32)>>>(wq, wk, wf, wTh, wTl);

    // fused q,k GEMM: B rows 0..511 = wq^T, 512..1023 = wk^T
    mma_gemm<0><<<dim3(8, MT), 256, GEMM_SMEM>>>(ah, al, wTh, wTl, bq, bk,
                                                 nullptr, q, k, nullptr, nullptr);
    // normalize
    l2norm_kernel<<<M_TOTAL, 128>>>(q, k, knh, knl);
    // gq = per-batch sum of qn
    zero_gq_kernel<<<(BATCH * DIM + 255) / 256, 256>>>(gq);
    batch_sum_kernel<<<dim3(DIM / 128, BATCH, SEQ / 256), 128>>>(q, gq);
    // per-batch scaled wp (transposed + split)
    wpsplit_kernel<<<dim3(16, 16, BATCH), dim3(32, 32)>>>(wp, gq, wpTh, wpTl);

    // u = kn @ (diag(gq_b) wp) + bp + qn  -> split into ah/al
    mma_gemm<1><<<dim3(4, MT), 256, GEMM_SMEM>>>(knh, knl, wpTh, wpTl, bp, nullptr,
                                                 q, nullptr, nullptr, ah, al);
    // out = u @ wf + bf
    mma_gemm<2><<<dim3(4, MT), 256, GEMM_SMEM>>>(ah, al, wTh + 2 * DIM * DIM, wTl + 2 * DIM * DIM,
                                                 bf, nullptr, nullptr, out, nullptr, nullptr, nullptr);
}

// round 6
// speedup vs baseline: 2.5100x; 1.1913x over previous
#include <cuda_runtime.h>
#include <cuda_bf16.h>
#include <cstdint>
#include <cstddef>

#define DIM     512
#define BATCH   8
#define SEQ     4096
#define M_TOTAL (BATCH * SEQ)   // 32768

// ---------------------------------------------------------------------------
// Scratch (__device__ globals; no allocation allowed)
// ---------------------------------------------------------------------------
__device__ __nv_bfloat16 g_ah[(size_t)M_TOTAL * DIM];   // x hi  -> later u hi
__device__ __nv_bfloat16 g_al[(size_t)M_TOTAL * DIM];   // x lo  -> later u lo
__device__ float         g_q [(size_t)M_TOTAL * DIM];   // q -> qn (in place)
__device__ float         g_k [(size_t)M_TOTAL * DIM];   // k (pre-norm)
__device__ __nv_bfloat16 g_knh[(size_t)M_TOTAL * DIM];  // k normalized hi
__device__ __nv_bfloat16 g_knl[(size_t)M_TOTAL * DIM];  // k normalized lo
__device__ __nv_bfloat16 g_wTh[3u * DIM * DIM];         // wq^T, wk^T, wf^T hi (concat rows)
__device__ __nv_bfloat16 g_wTl[3u * DIM * DIM];         // lo
__device__ __nv_bfloat16 g_wpTh[(size_t)BATCH * DIM * DIM]; // (diag(gq_b) wp)^T hi
__device__ __nv_bfloat16 g_wpTl[(size_t)BATCH * DIM * DIM]; // lo
__device__ float         g_gq[BATCH * DIM];

// ---------------------------------------------------------------------------
// helpers
// ---------------------------------------------------------------------------
__device__ __forceinline__ uint32_t smem_u32(const void* p) {
    uint32_t a;
    asm("{ .reg .u64 t; cvta.to.shared.u64 t, %1; cvt.u32.u64 %0, t; }" : "=r"(a) : "l"(p));
    return a;
}
__device__ __forceinline__ uint32_t swz(uint32_t o) { return o ^ ((o >> 3) & 0x70); }

__device__ __forceinline__ void cp16(uint32_t s, const void* g) {
    asm volatile("cp.async.cg.shared.global [%0], [%1], 16;\n" :: "r"(s), "l"(g));
}
#define CP_COMMIT() asm volatile("cp.async.commit_group;\n" ::: "memory")
#define CP_WAIT1()  asm volatile("cp.async.wait_group 1;\n" ::: "memory")

__device__ __forceinline__ void ldsm4(uint32_t* r, uint32_t addr) {
    asm volatile("ldmatrix.sync.aligned.m8n8.x4.shared.b16 {%0,%1,%2,%3}, [%4];\n"
                 : "=r"(r[0]), "=r"(r[1]), "=r"(r[2]), "=r"(r[3]) : "r"(addr));
}
__device__ __forceinline__ void mma16816(float* d, const uint32_t* a, const uint32_t* b) {
    asm volatile(
        "mma.sync.aligned.m16n8k16.row.col.f32.bf16.bf16.f32 "
        "{%0,%1,%2,%3}, {%4,%5,%6,%7}, {%8,%9}, {%0,%1,%2,%3};\n"
        : "+f"(d[0]), "+f"(d[1]), "+f"(d[2]), "+f"(d[3])
        : "r"(a[0]), "r"(a[1]), "r"(a[2]), "r"(a[3]), "r"(b[0]), "r"(b[1]));
}

__device__ __forceinline__ void split1(float v, __nv_bfloat16& h, __nv_bfloat16& l) {
    h = __float2bfloat16(v);
    l = __float2bfloat16(v - __bfloat162float(h));
}

// ---------------------------------------------------------------------------
// bf16-split GEMM:  C[M,N] = (Ah+Al)[M,512] @ (Bh+Bl)[N,512]^T (+bias)(+addend)
// Logical K' = 1536 = 24 chunks of 64:
//   chunks 0..7  : Ah x Bh    8..15 : Al x Bh    16..23 : Ah x Bl
// CTA 128x128, 8 warps (2M x 4N of 64x32 warp tiles), 3-stage cp.async,
// 2 CTAs/SM (192 KB smem total, <=128 regs).
// MODE 0: two fp32 outputs (cols <512 -> out0/bias0, >=512 -> out1/bias1)
// MODE 1: per-batch B, fp32 addend added, result split to (outH, outL) bf16
// MODE 2: single fp32 output + bias0
// ---------------------------------------------------------------------------
#define STAGES 3
#define CHUNKS 24
#define GEMM_SMEM (STAGES * 32768)   // 96 KB

__device__ __forceinline__ void load_chunk(
    const __nv_bfloat16* __restrict__ Ah, const __nv_bfloat16* __restrict__ Al,
    const __nv_bfloat16* __restrict__ Bh, const __nv_bfloat16* __restrict__ Bl,
    int m0, int n0, int c, uint32_t sA, uint32_t sB, int t)
{
    const __nv_bfloat16* Ap = (c < 8 || c >= 16) ? Ah : Al;
    const __nv_bfloat16* Bp = (c < 16) ? Bh : Bl;
    const int k0 = (c & 7) * 64;
    const int ch = t & 7;          // 16B chunk within 128B row
    const int rb = t >> 3;         // 0..31
#pragma unroll
    for (int it = 0; it < 4; it++) {
        int r = it * 32 + rb;
        cp16(sA + swz((uint32_t)(r * 128 + ch * 16)),
             Ap + (size_t)(m0 + r) * DIM + k0 + ch * 8);
    }
#pragma unroll
    for (int it = 0; it < 4; it++) {
        int r = it * 32 + rb;
        cp16(sB + swz((uint32_t)(r * 128 + ch * 16)),
             Bp + (size_t)(n0 + r) * DIM + k0 + ch * 8);
    }
}

template <int MODE>
__global__ __launch_bounds__(256, 2)
void mma_gemm(const __nv_bfloat16* __restrict__ Ah, const __nv_bfloat16* __restrict__ Al,
              const __nv_bfloat16* __restrict__ Bh, const __nv_bfloat16* __restrict__ Bl,
              const float* __restrict__ bias0, const float* __restrict__ bias1,
              const float* __restrict__ addend,
              float* __restrict__ out0, float* __restrict__ out1,
              __nv_bfloat16* __restrict__ outH, __nv_bfloat16* __restrict__ outL)
{
    extern __shared__ char smem[];
    const uint32_t sb = smem_u32(smem);
    const int t = threadIdx.x;
    const int w = t >> 5, l = t & 31;
    const int m0 = blockIdx.y * 128;
    const int n0 = blockIdx.x * 128;

    if (MODE == 1) {
        size_t bo = (size_t)(m0 / SEQ) * DIM * DIM;
        Bh += bo; Bl += bo;
    }

    uint32_t sA[STAGES], sB[STAGES];
#pragma unroll
    for (int s = 0; s < STAGES; s++) { sA[s] = sb + s * 32768u; sB[s] = sA[s] + 16384u; }

    // prologue: chunks 0,1
    load_chunk(Ah, Al, Bh, Bl, m0, n0, 0, sA[0], sB[0], t); CP_COMMIT();
    load_chunk(Ah, Al, Bh, Bl, m0, n0, 1, sA[1], sB[1], t); CP_COMMIT();

    const int wm = w & 1;          // M half (0/1) -> 64 rows
    const int wn = w >> 1;         // N quarter (0..3) -> 32 cols
    const uint32_t aBase = (uint32_t)((wm * 64 + (l & 15)) * 128 + (l >> 4) * 16);
    const uint32_t bBase = (uint32_t)((wn * 32 + ((l >> 4) * 8) + (l & 7)) * 128
                                      + ((l >> 3) & 1) * 16);

    float acc[4][4][4];
#pragma unroll
    for (int i = 0; i < 4; i++)
#pragma unroll
        for (int j = 0; j < 4; j++)
#pragma unroll
            for (int e = 0; e < 4; e++) acc[i][j][e] = 0.0f;

    for (int c = 0; c < CHUNKS; c++) {
        CP_WAIT1();
        __syncthreads();
        const int pf = c + 2;
        if (pf < CHUNKS)
            load_chunk(Ah, Al, Bh, Bl, m0, n0, pf, sA[pf % 3], sB[pf % 3], t);
        CP_COMMIT();

        const uint32_t cA = sA[c % 3], cB = sB[c % 3];
#pragma unroll
        for (int s = 0; s < 4; s++) {
            uint32_t a[4][4], b[4][2];
#pragma unroll
            for (int i = 0; i < 4; i++) {
                uint32_t off = aBase + i * 2048 + s * 32;
                ldsm4(a[i], cA + (off ^ ((off >> 3) & 0x70)));
            }
#pragma unroll
            for (int jj = 0; jj < 2; jj++) {
                uint32_t off = bBase + jj * 2048 + s * 32;
                uint32_t r[4];
                ldsm4(r, cB + (off ^ ((off >> 3) & 0x70)));
                b[2 * jj][0] = r[0]; b[2 * jj][1] = r[1];
                b[2 * jj + 1][0] = r[2]; b[2 * jj + 1][1] = r[3];
            }
#pragma unroll
            for (int i = 0; i < 4; i++)
#pragma unroll
                for (int j = 0; j < 4; j++)
                    mma16816(acc[i][j], a[i], b[j]);
        }
    }

    // ---- epilogue ----
    const float* bias = bias0;
    float* outp = out0;
    int cb = n0;
    if (MODE == 0 && n0 >= 512) { bias = bias1; outp = out1; cb = n0 - 512; }

    const int colw = cb + wn * 32 + (l & 3) * 2;
    float bj[4][2];
#pragma unroll
    for (int j = 0; j < 4; j++) {
        bj[j][0] = bias[colw + j * 8];
        bj[j][1] = bias[colw + j * 8 + 1];
    }

    const int mrow = m0 + wm * 64 + (l >> 2);
#pragma unroll
    for (int i = 0; i < 4; i++) {
        int r0 = mrow + i * 16, r1 = r0 + 8;
#pragma unroll
        for (int j = 0; j < 4; j++) {
            int cc = colw + j * 8;
            float v0 = acc[i][j][0] + bj[j][0];
            float v1 = acc[i][j][1] + bj[j][1];
            float v2 = acc[i][j][2] + bj[j][0];
            float v3 = acc[i][j][3] + bj[j][1];
            size_t o0 = (size_t)r0 * DIM + cc;
            size_t o1 = (size_t)r1 * DIM + cc;
            if (MODE == 1) {
                float2 a0 = *reinterpret_cast<const float2*>(addend + o0);
                float2 a1 = *reinterpret_cast<const float2*>(addend + o1);
                v0 += a0.x; v1 += a0.y; v2 += a1.x; v3 += a1.y;
                __nv_bfloat16 h0, h1, h2, h3, l0, l1, l2, l3;
                split1(v0, h0, l0); split1(v1, h1, l1);
                split1(v2, h2, l2); split1(v3, h3, l3);
                *reinterpret_cast<__nv_bfloat162*>(outH + o0) = __nv_bfloat162(h0, h1);
                *reinterpret_cast<__nv_bfloat162*>(outH + o1) = __nv_bfloat162(h2, h3);
                *reinterpret_cast<__nv_bfloat162*>(outL + o0) = __nv_bfloat162(l0, l1);
                *reinterpret_cast<__nv_bfloat162*>(outL + o1) = __nv_bfloat162(l2, l3);
            } else {
                *reinterpret_cast<float2*>(outp + o0) = make_float2(v0, v1);
                *reinterpret_cast<float2*>(outp + o1) = make_float2(v2, v3);
            }
        }
    }
}

// ---------------------------------------------------------------------------
// x -> bf16 hi/lo split
// ---------------------------------------------------------------------------
__global__ void split_x_kernel(const float* __restrict__ x,
                               __nv_bfloat16* __restrict__ h,
                               __nv_bfloat16* __restrict__ l)
{
    size_t i = (size_t)blockIdx.x * blockDim.x + threadIdx.x;   // float4 index
    float4 v = reinterpret_cast<const float4*>(x)[i];
    __nv_bfloat16 h0, h1, h2, h3, l0, l1, l2, l3;
    split1(v.x, h0, l0); split1(v.y, h1, l1); split1(v.z, h2, l2); split1(v.w, h3, l3);
    reinterpret_cast<__nv_bfloat162*>(h)[2 * i]     = __nv_bfloat162(h0, h1);
    reinterpret_cast<__nv_bfloat162*>(h)[2 * i + 1] = __nv_bfloat162(h2, h3);
    reinterpret_cast<__nv_bfloat162*>(l)[2 * i]     = __nv_bfloat162(l0, l1);
    reinterpret_cast<__nv_bfloat162*>(l)[2 * i + 1] = __nv_bfloat162(l2, l3);
}

// ---------------------------------------------------------------------------
// Transpose + split the three static weights: out[z][n][k] = split(w_z[k][n])
// ---------------------------------------------------------------------------
__global__ void wsplit_kernel(const float* __restrict__ wq,
                              const float* __restrict__ wk,
                              const float* __restrict__ wf,
                              __nv_bfloat16* __restrict__ th,
                              __nv_bfloat16* __restrict__ tl)
{
    __shared__ float sm[32][33];
    const int z = blockIdx.z;
    const float* w = (z == 0) ? wq : (z == 1) ? wk : wf;
    const int n0 = blockIdx.x * 32, k0 = blockIdx.y * 32;
    sm[threadIdx.y][threadIdx.x] = w[(size_t)(k0 + threadIdx.y) * DIM + n0 + threadIdx.x];
    __syncthreads();
    float v = sm[threadIdx.x][threadIdx.y];   // w[k0+tx][n0+ty]
    size_t o = (size_t)z * DIM * DIM + (size_t)(n0 + threadIdx.y) * DIM + k0 + threadIdx.x;
    __nv_bfloat16 h, l; split1(v, h, l);
    th[o] = h; tl[o] = l;
}

// out[b][n][k] = split(gq[b][k] * wp[k][n])
__global__ void wpsplit_kernel(const float* __restrict__ wp,
                               const float* __restrict__ gq,
                               __nv_bfloat16* __restrict__ th,
                               __nv_bfloat16* __restrict__ tl)
{
    __shared__ float sm[32][33];
    const int b = blockIdx.z;
    const int n0 = blockIdx.x * 32, k0 = blockIdx.y * 32;
    sm[threadIdx.y][threadIdx.x] = wp[(size_t)(k0 + threadIdx.y) * DIM + n0 + threadIdx.x];
    __syncthreads();
    float v = sm[threadIdx.x][threadIdx.y] * gq[b * DIM + k0 + threadIdx.x];
    size_t o = (size_t)b * DIM * DIM + (size_t)(n0 + threadIdx.y) * DIM + k0 + threadIdx.x;
    __nv_bfloat16 h, l; split1(v, h, l);
    th[o] = h; tl[o] = l;
}

// ---------------------------------------------------------------------------
// L2-normalize q (in place, fp32) and k (-> bf16 split). grid = M_TOTAL, 128 thr.
// ---------------------------------------------------------------------------
__global__ void l2norm_kernel(float* __restrict__ q, const float* __restrict__ k,
                              __nv_bfloat16* __restrict__ knh,
                              __nv_bfloat16* __restrict__ knl)
{
    const int row = blockIdx.x;
    const int tid = threadIdx.x;
    float4* qr = reinterpret_cast<float4*>(q + (size_t)row * DIM);
    const float4* kr = reinterpret_cast<const float4*>(k + (size_t)row * DIM);

    float4 qv = qr[tid];
    float4 kv = kr[tid];
    float sq = qv.x * qv.x + qv.y * qv.y + qv.z * qv.z + qv.w * qv.w;
    float sk = kv.x * kv.x + kv.y * kv.y + kv.z * kv.z + kv.w * kv.w;
#pragma unroll
    for (int o = 16; o > 0; o >>= 1) {
        sq += __shfl_xor_sync(0xFFFFFFFFu, sq, o);
        sk += __shfl_xor_sync(0xFFFFFFFFu, sk, o);
    }
    __shared__ float sh[8];
    const int wid = tid >> 5, lane = tid & 31;
    if (lane == 0) { sh[wid] = sq; sh[4 + wid] = sk; }
    __syncthreads();
    sq = sh[0] + sh[1] + sh[2] + sh[3];
    sk = sh[4] + sh[5] + sh[6] + sh[7];
    const float rq = rsqrtf(fmaxf(sq, 1e-12f));
    const float rk = rsqrtf(fmaxf(sk, 1e-12f));

    qv.x *= rq; qv.y *= rq; qv.z *= rq; qv.w *= rq;
    qr[tid] = qv;

    kv.x *= rk; kv.y *= rk; kv.z *= rk; kv.w *= rk;
    __nv_bfloat16 h0, h1, h2, h3, l0, l1, l2, l3;
    split1(kv.x, h0, l0); split1(kv.y, h1, l1); split1(kv.z, h2, l2); split1(kv.w, h3, l3);
    size_t o = (size_t)row * (DIM / 2) + tid * 2;
    reinterpret_cast<__nv_bfloat162*>(knh)[o]     = __nv_bfloat162(h0, h1);
    reinterpret_cast<__nv_bfloat162*>(knh)[o + 1] = __nv_bfloat162(h2, h3);
    reinterpret_cast<__nv_bfloat162*>(knl)[o]     = __nv_bfloat162(l0, l1);
    reinterpret_cast<__nv_bfloat162*>(knl)[o + 1] = __nv_bfloat162(l2, l3);
}

__global__ void zero_gq_kernel(float* __restrict__ gq)
{
    int i = blockIdx.x * blockDim.x + threadIdx.x;
    if (i < BATCH * DIM) gq[i] = 0.0f;
}

// gq[b,d] = sum_n qn[b,n,d]  -- float4 per thread, 128 threads cover all 512 d
__global__ void batch_sum_kernel(const float* __restrict__ qn, float* __restrict__ gq)
{
    const int d4 = threadIdx.x;                     // float4 index 0..127
    const int b  = blockIdx.y;
    const int n0 = blockIdx.z * 256;
    const float4* base = reinterpret_cast<const float4*>(
        qn + ((size_t)b * SEQ + n0) * DIM) + d4;
    float4 s = make_float4(0.f, 0.f, 0.f, 0.f);
#pragma unroll 8
    for (int i = 0; i < 256; i++) {
        float4 v = base[(size_t)i * (DIM / 4)];
        s.x += v.x; s.y += v.y; s.z += v.z; s.w += v.w;
    }
    float* g = gq + b * DIM + d4 * 4;
    atomicAdd(g + 0, s.x);
    atomicAdd(g + 1, s.y);
    atomicAdd(g + 2, s.z);
    atomicAdd(g + 3, s.w);
}

// ---------------------------------------------------------------------------
extern "C" void kernel_launch(void* const* d_in, const int* in_sizes, int n_in,
                              void* d_out, int out_size)
{
    const float* x  = (const float*)d_in[0];
    const float* wq = (const float*)d_in[1];
    const float* bq = (const float*)d_in[2];
    const float* wk = (const float*)d_in[3];
    const float* bk = (const float*)d_in[4];
    const float* wp = (const float*)d_in[5];
    const float* bp = (const float*)d_in[6];
    const float* wf = (const float*)d_in[7];
    const float* bf = (const float*)d_in[8];
    // d_in[9] = w_g: softmax over size-1 axis == 1 -> unused
    float* out = (float*)d_out;

    __nv_bfloat16 *ah, *al, *knh, *knl, *wTh, *wTl, *wpTh, *wpTl;
    float *q, *k, *gq;
    cudaGetSymbolAddress((void**)&ah,  g_ah);
    cudaGetSymbolAddress((void**)&al,  g_al);
    cudaGetSymbolAddress((void**)&q,   g_q);
    cudaGetSymbolAddress((void**)&k,   g_k);
    cudaGetSymbolAddress((void**)&knh, g_knh);
    cudaGetSymbolAddress((void**)&knl, g_knl);
    cudaGetSymbolAddress((void**)&wTh, g_wTh);
    cudaGetSymbolAddress((void**)&wTl, g_wTl);
    cudaGetSymbolAddress((void**)&wpTh, g_wpTh);
    cudaGetSymbolAddress((void**)&wpTl, g_wpTl);
    cudaGetSymbolAddress((void**)&gq,  g_gq);

    cudaFuncSetAttribute(mma_gemm<0>, cudaFuncAttributeMaxDynamicSharedMemorySize, GEMM_SMEM);
    cudaFuncSetAttribute(mma_gemm<1>, cudaFuncAttributeMaxDynamicSharedMemorySize, GEMM_SMEM);
    cudaFuncSetAttribute(mma_gemm<2>, cudaFuncAttributeMaxDynamicSharedMemorySize, GEMM_SMEM);

    const int MT = M_TOTAL / 128;   // 256 row tiles

    // split x into bf16 hi/lo
    split_x_kernel<<<(size_t)M_TOTAL * DIM / 4 / 256, 256>>>(x, ah, al);
    // transpose + split static weights (wq^T | wk^T | wf^T concatenated)
    wsplit_kernel<<<dim3(16, 16, 3), dim3(32, 32)>>>(wq, wk, wf, wTh, wTl);

    // fused q,k GEMM: B rows 0..511 = wq^T, 512..1023 = wk^T
    mma_gemm<0><<<dim3(8, MT), 256, GEMM_SMEM>>>(ah, al, wTh, wTl, bq, bk,
                                                 nullptr, q, k, nullptr, nullptr);
    // normalize
    l2norm_kernel<<<M_TOTAL, 128>>>(q, k, knh, knl);
    // gq = per-batch sum of qn
    zero_gq_kernel<<<(BATCH * DIM + 255) / 256, 256>>>(gq);
    batch_sum_kernel<<<dim3(1, BATCH, SEQ / 256), 128>>>(q, gq);
    // per-batch scaled wp (transposed + split)
    wpsplit_kernel<<<dim3(16, 16, BATCH), dim3(32, 32)>>>(wp, gq, wpTh, wpTl);

    // u = kn @ (diag(gq_b) wp) + bp + qn  -> split into ah/al
    mma_gemm<1><<<dim3(4, MT), 256, GEMM_SMEM>>>(knh, knl, wpTh, wpTl, bp, nullptr,
                                                 q, nullptr, nullptr, ah, al);
    // out = u @ wf + bf
    mma_gemm<2><<<dim3(4, MT), 256, GEMM_SMEM>>>(ah, al, wTh + 2 * DIM * DIM, wTl + 2 * DIM * DIM,
                                                 bf, nullptr, nullptr, out, nullptr, nullptr, nullptr);
}

// round 7
// speedup vs baseline: 5.2052x; 2.0738x over previous
#include <cuda_runtime.h>
#include <cuda_fp16.h>
#include <cstdint>
#include <cstddef>

#define DIM     512
#define BATCH   8
#define SEQ     4096
#define M_TOTAL (BATCH * SEQ)   // 32768

// ---------------------------------------------------------------------------
// Scratch (__device__ globals; no allocation allowed)
// ---------------------------------------------------------------------------
__device__ __half  g_xh[(size_t)M_TOTAL * DIM];   // x fp16  -> later u fp16
__device__ float   g_q [(size_t)M_TOTAL * DIM];   // q -> qn (in place)
__device__ float   g_k [(size_t)M_TOTAL * DIM];   // k (pre-norm)
__device__ __half  g_kn[(size_t)M_TOTAL * DIM];   // k normalized fp16
__device__ __half  g_wT[3u * DIM * DIM];          // wq^T, wk^T, wf^T fp16 (concat rows)
__device__ __half  g_wpT[(size_t)BATCH * DIM * DIM]; // (diag(gq_b) wp)^T fp16
__device__ float   g_gq[BATCH * DIM];

// ---------------------------------------------------------------------------
// helpers
// ---------------------------------------------------------------------------
__device__ __forceinline__ uint32_t smem_u32(const void* p) {
    uint32_t a;
    asm("{ .reg .u64 t; cvta.to.shared.u64 t, %1; cvt.u32.u64 %0, t; }" : "=r"(a) : "l"(p));
    return a;
}
__device__ __forceinline__ uint32_t swz(uint32_t o) { return o ^ ((o >> 3) & 0x70); }

__device__ __forceinline__ void cp16(uint32_t s, const void* g) {
    asm volatile("cp.async.cg.shared.global [%0], [%1], 16;\n" :: "r"(s), "l"(g));
}
#define CP_COMMIT() asm volatile("cp.async.commit_group;\n" ::: "memory")
#define CP_WAIT1()  asm volatile("cp.async.wait_group 1;\n" ::: "memory")

__device__ __forceinline__ void ldsm4(uint32_t* r, uint32_t addr) {
    asm volatile("ldmatrix.sync.aligned.m8n8.x4.shared.b16 {%0,%1,%2,%3}, [%4];\n"
                 : "=r"(r[0]), "=r"(r[1]), "=r"(r[2]), "=r"(r[3]) : "r"(addr));
}
__device__ __forceinline__ void mma16816(float* d, const uint32_t* a, const uint32_t* b) {
    asm volatile(
        "mma.sync.aligned.m16n8k16.row.col.f32.f16.f16.f32 "
        "{%0,%1,%2,%3}, {%4,%5,%6,%7}, {%8,%9}, {%0,%1,%2,%3};\n"
        : "+f"(d[0]), "+f"(d[1]), "+f"(d[2]), "+f"(d[3])
        : "r"(a[0]), "r"(a[1]), "r"(a[2]), "r"(a[3]), "r"(b[0]), "r"(b[1]));
}

// ---------------------------------------------------------------------------
// fp16 GEMM:  C[M,N] = A[M,512] @ B[N,512]^T (+bias)(+addend)   K-major B = [N,K]
// 8 chunks of K=64. CTA 128x128, 8 warps (2M x 4N of 64x32 warp tiles),
// 3-stage cp.async, 2 CTAs/SM (96 KB smem/CTA).
// MODE 0: two fp32 outputs (cols <512 -> out0/bias0, >=512 -> out1/bias1)
// MODE 1: per-batch B, fp32 addend added, result written fp16 to outH
// MODE 2: single fp32 output + bias0
// ---------------------------------------------------------------------------
#define STAGES 3
#define CHUNKS 8
#define GEMM_SMEM (STAGES * 32768)   // 96 KB

__device__ __forceinline__ void load_chunk(
    const __half* __restrict__ A, const __half* __restrict__ B,
    int m0, int n0, int c, uint32_t sA, uint32_t sB, int t)
{
    const int k0 = c * 64;
    const int ch = t & 7;          // 16B chunk within 128B row
    const int rb = t >> 3;         // 0..31
#pragma unroll
    for (int it = 0; it < 4; it++) {
        int r = it * 32 + rb;
        cp16(sA + swz((uint32_t)(r * 128 + ch * 16)),
             A + (size_t)(m0 + r) * DIM + k0 + ch * 8);
    }
#pragma unroll
    for (int it = 0; it < 4; it++) {
        int r = it * 32 + rb;
        cp16(sB + swz((uint32_t)(r * 128 + ch * 16)),
             B + (size_t)(n0 + r) * DIM + k0 + ch * 8);
    }
}

template <int MODE>
__global__ __launch_bounds__(256, 2)
void mma_gemm(const __half* __restrict__ A, const __half* __restrict__ B,
              const float* __restrict__ bias0, const float* __restrict__ bias1,
              const float* __restrict__ addend,
              float* __restrict__ out0, float* __restrict__ out1,
              __half* __restrict__ outH)
{
    extern __shared__ char smem[];
    const uint32_t sb = smem_u32(smem);
    const int t = threadIdx.x;
    const int w = t >> 5, l = t & 31;
    const int m0 = blockIdx.y * 128;
    const int n0 = blockIdx.x * 128;

    if (MODE == 1)
        B += (size_t)(m0 / SEQ) * DIM * DIM;

    uint32_t sA[STAGES], sB[STAGES];
#pragma unroll
    for (int s = 0; s < STAGES; s++) { sA[s] = sb + s * 32768u; sB[s] = sA[s] + 16384u; }

    // prologue: chunks 0,1
    load_chunk(A, B, m0, n0, 0, sA[0], sB[0], t); CP_COMMIT();
    load_chunk(A, B, m0, n0, 1, sA[1], sB[1], t); CP_COMMIT();

    const int wm = w & 1;          // M half (0/1) -> 64 rows
    const int wn = w >> 1;         // N quarter (0..3) -> 32 cols
    const uint32_t aBase = (uint32_t)((wm * 64 + (l & 15)) * 128 + (l >> 4) * 16);
    const uint32_t bBase = (uint32_t)((wn * 32 + ((l >> 4) * 8) + (l & 7)) * 128
                                      + ((l >> 3) & 1) * 16);

    float acc[4][4][4];
#pragma unroll
    for (int i = 0; i < 4; i++)
#pragma unroll
        for (int j = 0; j < 4; j++)
#pragma unroll
            for (int e = 0; e < 4; e++) acc[i][j][e] = 0.0f;

    for (int c = 0; c < CHUNKS; c++) {
        CP_WAIT1();
        __syncthreads();
        const int pf = c + 2;
        if (pf < CHUNKS)
            load_chunk(A, B, m0, n0, pf, sA[pf % 3], sB[pf % 3], t);
        CP_COMMIT();

        const uint32_t cA = sA[c % 3], cB = sB[c % 3];
#pragma unroll
        for (int s = 0; s < 4; s++) {
            uint32_t a[4][4], b[4][2];
#pragma unroll
            for (int i = 0; i < 4; i++) {
                uint32_t off = aBase + i * 2048 + s * 32;
                ldsm4(a[i], cA + (off ^ ((off >> 3) & 0x70)));
            }
#pragma unroll
            for (int jj = 0; jj < 2; jj++) {
                uint32_t off = bBase + jj * 2048 + s * 32;
                uint32_t r[4];
                ldsm4(r, cB + (off ^ ((off >> 3) & 0x70)));
                b[2 * jj][0] = r[0]; b[2 * jj][1] = r[1];
                b[2 * jj + 1][0] = r[2]; b[2 * jj + 1][1] = r[3];
            }
#pragma unroll
            for (int i = 0; i < 4; i++)
#pragma unroll
                for (int j = 0; j < 4; j++)
                    mma16816(acc[i][j], a[i], b[j]);
        }
    }

    // ---- epilogue ----
    const float* bias = bias0;
    float* outp = out0;
    int cb = n0;
    if (MODE == 0 && n0 >= 512) { bias = bias1; outp = out1; cb = n0 - 512; }

    const int colw = cb + wn * 32 + (l & 3) * 2;
    float bj[4][2];
#pragma unroll
    for (int j = 0; j < 4; j++) {
        bj[j][0] = bias[colw + j * 8];
        bj[j][1] = bias[colw + j * 8 + 1];
    }

    const int mrow = m0 + wm * 64 + (l >> 2);
#pragma unroll
    for (int i = 0; i < 4; i++) {
        int r0 = mrow + i * 16, r1 = r0 + 8;
#pragma unroll
        for (int j = 0; j < 4; j++) {
            int cc = colw + j * 8;
            float v0 = acc[i][j][0] + bj[j][0];
            float v1 = acc[i][j][1] + bj[j][1];
            float v2 = acc[i][j][2] + bj[j][0];
            float v3 = acc[i][j][3] + bj[j][1];
            size_t o0 = (size_t)r0 * DIM + cc;
            size_t o1 = (size_t)r1 * DIM + cc;
            if (MODE == 1) {
                float2 a0 = *reinterpret_cast<const float2*>(addend + o0);
                float2 a1 = *reinterpret_cast<const float2*>(addend + o1);
                v0 += a0.x; v1 += a0.y; v2 += a1.x; v3 += a1.y;
                *reinterpret_cast<__half2*>(outH + o0) = __floats2half2_rn(v0, v1);
                *reinterpret_cast<__half2*>(outH + o1) = __floats2half2_rn(v2, v3);
            } else {
                *reinterpret_cast<float2*>(outp + o0) = make_float2(v0, v1);
                *reinterpret_cast<float2*>(outp + o1) = make_float2(v2, v3);
            }
        }
    }
}

// ---------------------------------------------------------------------------
// x -> fp16
// ---------------------------------------------------------------------------
__global__ void cvt_x_kernel(const float* __restrict__ x, __half* __restrict__ h)
{
    size_t i = (size_t)blockIdx.x * blockDim.x + threadIdx.x;   // float4 index
    float4 v = reinterpret_cast<const float4*>(x)[i];
    reinterpret_cast<__half2*>(h)[2 * i]     = __floats2half2_rn(v.x, v.y);
    reinterpret_cast<__half2*>(h)[2 * i + 1] = __floats2half2_rn(v.z, v.w);
}

// ---------------------------------------------------------------------------
// Transpose + convert the three static weights: out[z][n][k] = fp16(w_z[k][n])
// ---------------------------------------------------------------------------
__global__ void wsplit_kernel(const float* __restrict__ wq,
                              const float* __restrict__ wk,
                              const float* __restrict__ wf,
                              __half* __restrict__ th)
{
    __shared__ float sm[32][33];
    const int z = blockIdx.z;
    const float* w = (z == 0) ? wq : (z == 1) ? wk : wf;
    const int n0 = blockIdx.x * 32, k0 = blockIdx.y * 32;
    sm[threadIdx.y][threadIdx.x] = w[(size_t)(k0 + threadIdx.y) * DIM + n0 + threadIdx.x];
    __syncthreads();
    float v = sm[threadIdx.x][threadIdx.y];   // w[k0+tx][n0+ty]
    size_t o = (size_t)z * DIM * DIM + (size_t)(n0 + threadIdx.y) * DIM + k0 + threadIdx.x;
    th[o] = __float2half_rn(v);
}

// out[b][n][k] = fp16(gq[b][k] * wp[k][n])
__global__ void wpsplit_kernel(const float* __restrict__ wp,
                               const float* __restrict__ gq,
                               __half* __restrict__ th)
{
    __shared__ float sm[32][33];
    const int b = blockIdx.z;
    const int n0 = blockIdx.x * 32, k0 = blockIdx.y * 32;
    sm[threadIdx.y][threadIdx.x] = wp[(size_t)(k0 + threadIdx.y) * DIM + n0 + threadIdx.x];
    __syncthreads();
    float v = sm[threadIdx.x][threadIdx.y] * gq[b * DIM + k0 + threadIdx.x];
    size_t o = (size_t)b * DIM * DIM + (size_t)(n0 + threadIdx.y) * DIM + k0 + threadIdx.x;
    th[o] = __float2half_rn(v);
}

// ---------------------------------------------------------------------------
// L2-normalize q (in place, fp32) and k (-> fp16). grid = M_TOTAL, 128 thr.
// ---------------------------------------------------------------------------
__global__ void l2norm_kernel(float* __restrict__ q, const float* __restrict__ k,
                              __half* __restrict__ kn)
{
    const int row = blockIdx.x;
    const int tid = threadIdx.x;
    float4* qr = reinterpret_cast<float4*>(q + (size_t)row * DIM);
    const float4* kr = reinterpret_cast<const float4*>(k + (size_t)row * DIM);

    float4 qv = qr[tid];
    float4 kv = kr[tid];
    float sq = qv.x * qv.x + qv.y * qv.y + qv.z * qv.z + qv.w * qv.w;
    float sk = kv.x * kv.x + kv.y * kv.y + kv.z * kv.z + kv.w * kv.w;
#pragma unroll
    for (int o = 16; o > 0; o >>= 1) {
        sq += __shfl_xor_sync(0xFFFFFFFFu, sq, o);
        sk += __shfl_xor_sync(0xFFFFFFFFu, sk, o);
    }
    __shared__ float sh[8];
    const int wid = tid >> 5, lane = tid & 31;
    if (lane == 0) { sh[wid] = sq; sh[4 + wid] = sk; }
    __syncthreads();
    sq = sh[0] + sh[1] + sh[2] + sh[3];
    sk = sh[4] + sh[5] + sh[6] + sh[7];
    const float rq = rsqrtf(fmaxf(sq, 1e-12f));
    const float rk = rsqrtf(fmaxf(sk, 1e-12f));

    qv.x *= rq; qv.y *= rq; qv.z *= rq; qv.w *= rq;
    qr[tid] = qv;

    kv.x *= rk; kv.y *= rk; kv.z *= rk; kv.w *= rk;
    size_t o = (size_t)row * (DIM / 2) + tid * 2;
    reinterpret_cast<__half2*>(kn)[o]     = __floats2half2_rn(kv.x, kv.y);
    reinterpret_cast<__half2*>(kn)[o + 1] = __floats2half2_rn(kv.z, kv.w);
}

__global__ void zero_gq_kernel(float* __restrict__ gq)
{
    int i = blockIdx.x * blockDim.x + threadIdx.x;
    if (i < BATCH * DIM) gq[i] = 0.0f;
}

// gq[b,d] = sum_n qn[b,n,d]  -- float4 per thread, 128 threads cover all 512 d
__global__ void batch_sum_kernel(const float* __restrict__ qn, float* __restrict__ gq)
{
    const int d4 = threadIdx.x;                     // float4 index 0..127
    const int b  = blockIdx.y;
    const int n0 = blockIdx.z * 256;
    const float4* base = reinterpret_cast<const float4*>(
        qn + ((size_t)b * SEQ + n0) * DIM) + d4;
    float4 s = make_float4(0.f, 0.f, 0.f, 0.f);
#pragma unroll 8
    for (int i = 0; i < 256; i++) {
        float4 v = base[(size_t)i * (DIM / 4)];
        s.x += v.x; s.y += v.y; s.z += v.z; s.w += v.w;
    }
    float* g = gq + b * DIM + d4 * 4;
    atomicAdd(g + 0, s.x);
    atomicAdd(g + 1, s.y);
    atomicAdd(g + 2, s.z);
    atomicAdd(g + 3, s.w);
}

// ---------------------------------------------------------------------------
extern "C" void kernel_launch(void* const* d_in, const int* in_sizes, int n_in,
                              void* d_out, int out_size)
{
    const float* x  = (const float*)d_in[0];
    const float* wq = (const float*)d_in[1];
    const float* bq = (const float*)d_in[2];
    const float* wk = (const float*)d_in[3];
    const float* bk = (const float*)d_in[4];
    const float* wp = (const float*)d_in[5];
    const float* bp = (const float*)d_in[6];
    const float* wf = (const float*)d_in[7];
    const float* bf = (const float*)d_in[8];
    // d_in[9] = w_g: softmax over size-1 axis == 1 -> unused
    float* out = (float*)d_out;

    __half *xh, *kn, *wT, *wpT;
    float *q, *k, *gq;
    cudaGetSymbolAddress((void**)&xh,  g_xh);
    cudaGetSymbolAddress((void**)&q,   g_q);
    cudaGetSymbolAddress((void**)&k,   g_k);
    cudaGetSymbolAddress((void**)&kn,  g_kn);
    cudaGetSymbolAddress((void**)&wT,  g_wT);
    cudaGetSymbolAddress((void**)&wpT, g_wpT);
    cudaGetSymbolAddress((void**)&gq,  g_gq);

    cudaFuncSetAttribute(mma_gemm<0>, cudaFuncAttributeMaxDynamicSharedMemorySize, GEMM_SMEM);
    cudaFuncSetAttribute(mma_gemm<1>, cudaFuncAttributeMaxDynamicSharedMemorySize, GEMM_SMEM);
    cudaFuncSetAttribute(mma_gemm<2>, cudaFuncAttributeMaxDynamicSharedMemorySize, GEMM_SMEM);

    const int MT = M_TOTAL / 128;   // 256 row tiles

    // x -> fp16
    cvt_x_kernel<<<(size_t)M_TOTAL * DIM / 4 / 256, 256>>>(x, xh);
    // transpose + convert static weights (wq^T | wk^T | wf^T concatenated)
    wsplit_kernel<<<dim3(16, 16, 3), dim3(32, 32)>>>(wq, wk, wf, wT);

    // fused q,k GEMM: B rows 0..511 = wq^T, 512..1023 = wk^T
    mma_gemm<0><<<dim3(8, MT), 256, GEMM_SMEM>>>(xh, wT, bq, bk,
                                                 nullptr, q, k, nullptr);
    // normalize
    l2norm_kernel<<<M_TOTAL, 128>>>(q, k, kn);
    // gq = per-batch sum of qn
    zero_gq_kernel<<<(BATCH * DIM + 255) / 256, 256>>>(gq);
    batch_sum_kernel<<<dim3(1, BATCH, SEQ / 256), 128>>>(q, gq);
    // per-batch scaled wp (transposed, fp16)
    wpsplit_kernel<<<dim3(16, 16, BATCH), dim3(32, 32)>>>(wp, gq, wpT);

    // u = kn @ (diag(gq_b) wp) + bp + qn  -> fp16 into xh (x no longer needed)
    mma_gemm<1><<<dim3(4, MT), 256, GEMM_SMEM>>>(kn, wpT, bp, nullptr,
                                                 q, nullptr, nullptr, xh);
    // out = u @ wf + bf
    mma_gemm<2><<<dim3(4, MT), 256, GEMM_SMEM>>>(xh, wT + 2u * DIM * DIM, bf, nullptr,
                                                 nullptr, out, nullptr, nullptr);
}

// round 8
// speedup vs baseline: 5.9593x; 1.1449x over previous
#include <cuda_runtime.h>
#include <cuda_fp16.h>
#include <cstdint>
#include <cstddef>

#define DIM     512
#define BATCH   8
#define SEQ     4096
#define M_TOTAL (BATCH * SEQ)   // 32768

// ---------------------------------------------------------------------------
// Scratch (__device__ globals; no allocation allowed)
// ---------------------------------------------------------------------------
__device__ __half  g_xh[(size_t)M_TOTAL * DIM];   // x fp16  -> later u fp16
__device__ __half  g_qh[(size_t)M_TOTAL * DIM];   // q -> qn (fp16, in place)
__device__ __half  g_kh[(size_t)M_TOTAL * DIM];   // k -> kn (fp16, in place)
__device__ __half  g_wT[3u * DIM * DIM];          // wq^T, wk^T, wf^T fp16 (concat rows)
__device__ __half  g_wpT[(size_t)BATCH * DIM * DIM]; // (diag(gq_b) wp)^T fp16
__device__ float   g_gq[BATCH * DIM];

// ---------------------------------------------------------------------------
// helpers
// ---------------------------------------------------------------------------
__device__ __forceinline__ uint32_t smem_u32(const void* p) {
    uint32_t a;
    asm("{ .reg .u64 t; cvta.to.shared.u64 t, %1; cvt.u32.u64 %0, t; }" : "=r"(a) : "l"(p));
    return a;
}
__device__ __forceinline__ uint32_t swz(uint32_t o) { return o ^ ((o >> 3) & 0x70); }

__device__ __forceinline__ void cp16(uint32_t s, const void* g) {
    asm volatile("cp.async.cg.shared.global [%0], [%1], 16;\n" :: "r"(s), "l"(g));
}
#define CP_COMMIT() asm volatile("cp.async.commit_group;\n" ::: "memory")
#define CP_WAIT1()  asm volatile("cp.async.wait_group 1;\n" ::: "memory")

__device__ __forceinline__ void ldsm4(uint32_t* r, uint32_t addr) {
    asm volatile("ldmatrix.sync.aligned.m8n8.x4.shared.b16 {%0,%1,%2,%3}, [%4];\n"
                 : "=r"(r[0]), "=r"(r[1]), "=r"(r[2]), "=r"(r[3]) : "r"(addr));
}
__device__ __forceinline__ void mma16816(float* d, const uint32_t* a, const uint32_t* b) {
    asm volatile(
        "mma.sync.aligned.m16n8k16.row.col.f32.f16.f16.f32 "
        "{%0,%1,%2,%3}, {%4,%5,%6,%7}, {%8,%9}, {%0,%1,%2,%3};\n"
        : "+f"(d[0]), "+f"(d[1]), "+f"(d[2]), "+f"(d[3])
        : "r"(a[0]), "r"(a[1]), "r"(a[2]), "r"(a[3]), "r"(b[0]), "r"(b[1]));
}

// ---------------------------------------------------------------------------
// fp16 GEMM:  C[M,N] = A[M,512] @ B[N,512]^T (+bias)(+addend)   K-major B = [N,K]
// 8 chunks of K=64. CTA 128x128, 8 warps (2M x 4N of 64x32 warp tiles),
// 3-stage cp.async, 2 CTAs/SM (96 KB smem/CTA).
// MODE 0: two fp16 outputs (cols <512 -> out0h/bias0, >=512 -> out1h/bias1)
// MODE 1: per-batch B, fp16 addend added, result written fp16 to out0h
// MODE 2: single fp32 output + bias0
// ---------------------------------------------------------------------------
#define STAGES 3
#define CHUNKS 8
#define GEMM_SMEM (STAGES * 32768)   // 96 KB

__device__ __forceinline__ void load_chunk(
    const __half* __restrict__ A, const __half* __restrict__ B,
    int m0, int n0, int c, uint32_t sA, uint32_t sB, int t)
{
    const int k0 = c * 64;
    const int ch = t & 7;          // 16B chunk within 128B row
    const int rb = t >> 3;         // 0..31
#pragma unroll
    for (int it = 0; it < 4; it++) {
        int r = it * 32 + rb;
        cp16(sA + swz((uint32_t)(r * 128 + ch * 16)),
             A + (size_t)(m0 + r) * DIM + k0 + ch * 8);
    }
#pragma unroll
    for (int it = 0; it < 4; it++) {
        int r = it * 32 + rb;
        cp16(sB + swz((uint32_t)(r * 128 + ch * 16)),
             B + (size_t)(n0 + r) * DIM + k0 + ch * 8);
    }
}

template <int MODE>
__global__ __launch_bounds__(256, 2)
void mma_gemm(const __half* __restrict__ A, const __half* __restrict__ B,
              const float* __restrict__ bias0, const float* __restrict__ bias1,
              const __half* __restrict__ addH,
              float* __restrict__ outF,
              __half* __restrict__ out0h, __half* __restrict__ out1h)
{
    extern __shared__ char smem[];
    const uint32_t sb = smem_u32(smem);
    const int t = threadIdx.x;
    const int w = t >> 5, l = t & 31;
    const int m0 = blockIdx.y * 128;
    const int n0 = blockIdx.x * 128;

    if (MODE == 1)
        B += (size_t)(m0 / SEQ) * DIM * DIM;

    uint32_t sA[STAGES], sB[STAGES];
#pragma unroll
    for (int s = 0; s < STAGES; s++) { sA[s] = sb + s * 32768u; sB[s] = sA[s] + 16384u; }

    // prologue: chunks 0,1
    load_chunk(A, B, m0, n0, 0, sA[0], sB[0], t); CP_COMMIT();
    load_chunk(A, B, m0, n0, 1, sA[1], sB[1], t); CP_COMMIT();

    const int wm = w & 1;          // M half (0/1) -> 64 rows
    const int wn = w >> 1;         // N quarter (0..3) -> 32 cols
    const uint32_t aBase = (uint32_t)((wm * 64 + (l & 15)) * 128 + (l >> 4) * 16);
    const uint32_t bBase = (uint32_t)((wn * 32 + ((l >> 4) * 8) + (l & 7)) * 128
                                      + ((l >> 3) & 1) * 16);

    float acc[4][4][4];
#pragma unroll
    for (int i = 0; i < 4; i++)
#pragma unroll
        for (int j = 0; j < 4; j++)
#pragma unroll
            for (int e = 0; e < 4; e++) acc[i][j][e] = 0.0f;

    for (int c = 0; c < CHUNKS; c++) {
        CP_WAIT1();
        __syncthreads();
        const int pf = c + 2;
        if (pf < CHUNKS)
            load_chunk(A, B, m0, n0, pf, sA[pf % 3], sB[pf % 3], t);
        CP_COMMIT();

        const uint32_t cA = sA[c % 3], cB = sB[c % 3];
#pragma unroll
        for (int s = 0; s < 4; s++) {
            uint32_t a[4][4], b[4][2];
#pragma unroll
            for (int i = 0; i < 4; i++) {
                uint32_t off = aBase + i * 2048 + s * 32;
                ldsm4(a[i], cA + (off ^ ((off >> 3) & 0x70)));
            }
#pragma unroll
            for (int jj = 0; jj < 2; jj++) {
                uint32_t off = bBase + jj * 2048 + s * 32;
                uint32_t r[4];
                ldsm4(r, cB + (off ^ ((off >> 3) & 0x70)));
                b[2 * jj][0] = r[0]; b[2 * jj][1] = r[1];
                b[2 * jj + 1][0] = r[2]; b[2 * jj + 1][1] = r[3];
            }
#pragma unroll
            for (int i = 0; i < 4; i++)
#pragma unroll
                for (int j = 0; j < 4; j++)
                    mma16816(acc[i][j], a[i], b[j]);
        }
    }

    // ---- epilogue ----
    const float* bias = bias0;
    __half* outh = out0h;
    int cb = n0;
    if (MODE == 0 && n0 >= 512) { bias = bias1; outh = out1h; cb = n0 - 512; }

    const int colw = cb + wn * 32 + (l & 3) * 2;
    float bj[4][2];
#pragma unroll
    for (int j = 0; j < 4; j++) {
        bj[j][0] = bias[colw + j * 8];
        bj[j][1] = bias[colw + j * 8 + 1];
    }

    const int mrow = m0 + wm * 64 + (l >> 2);
#pragma unroll
    for (int i = 0; i < 4; i++) {
        int r0 = mrow + i * 16, r1 = r0 + 8;
#pragma unroll
        for (int j = 0; j < 4; j++) {
            int cc = colw + j * 8;
            float v0 = acc[i][j][0] + bj[j][0];
            float v1 = acc[i][j][1] + bj[j][1];
            float v2 = acc[i][j][2] + bj[j][0];
            float v3 = acc[i][j][3] + bj[j][1];
            size_t o0 = (size_t)r0 * DIM + cc;
            size_t o1 = (size_t)r1 * DIM + cc;
            if (MODE == 1) {
                float2 a0 = __half22float2(*reinterpret_cast<const __half2*>(addH + o0));
                float2 a1 = __half22float2(*reinterpret_cast<const __half2*>(addH + o1));
                v0 += a0.x; v1 += a0.y; v2 += a1.x; v3 += a1.y;
            }
            if (MODE == 2) {
                *reinterpret_cast<float2*>(outF + o0) = make_float2(v0, v1);
                *reinterpret_cast<float2*>(outF + o1) = make_float2(v2, v3);
            } else {
                *reinterpret_cast<__half2*>(outh + o0) = __floats2half2_rn(v0, v1);
                *reinterpret_cast<__half2*>(outh + o1) = __floats2half2_rn(v2, v3);
            }
        }
    }
}

// ---------------------------------------------------------------------------
// x -> fp16 (partial grid; base = float4 offset)
// ---------------------------------------------------------------------------
__global__ void cvt_x_kernel(const float* __restrict__ x, __half* __restrict__ h,
                             size_t base)
{
    size_t i = base + (size_t)blockIdx.x * blockDim.x + threadIdx.x;   // float4 index
    float4 v = reinterpret_cast<const float4*>(x)[i];
    reinterpret_cast<__half2*>(h)[2 * i]     = __floats2half2_rn(v.x, v.y);
    reinterpret_cast<__half2*>(h)[2 * i + 1] = __floats2half2_rn(v.z, v.w);
}

// ---------------------------------------------------------------------------
// Transpose + convert weights: th[(zoff+z)*D*D + n*D + k] = fp16(w_z[k][n])
// ---------------------------------------------------------------------------
__global__ void wsplit_kernel(const float* __restrict__ w0,
                              const float* __restrict__ w1,
                              __half* __restrict__ th, int zoff)
{
    __shared__ float sm[32][33];
    const int z = blockIdx.z;
    const float* w = (z == 0) ? w0 : w1;
    const int n0 = blockIdx.x * 32, k0 = blockIdx.y * 32;
    sm[threadIdx.y][threadIdx.x] = w[(size_t)(k0 + threadIdx.y) * DIM + n0 + threadIdx.x];
    __syncthreads();
    float v = sm[threadIdx.x][threadIdx.y];   // w[k0+tx][n0+ty]
    size_t o = (size_t)(zoff + z) * DIM * DIM + (size_t)(n0 + threadIdx.y) * DIM + k0 + threadIdx.x;
    th[o] = __float2half_rn(v);
}

// out[b][n][k] = fp16(gq[b][k] * wp[k][n])
__global__ void wpsplit_kernel(const float* __restrict__ wp,
                               const float* __restrict__ gq,
                               __half* __restrict__ th)
{
    __shared__ float sm[32][33];
    const int b = blockIdx.z;
    const int n0 = blockIdx.x * 32, k0 = blockIdx.y * 32;
    sm[threadIdx.y][threadIdx.x] = wp[(size_t)(k0 + threadIdx.y) * DIM + n0 + threadIdx.x];
    __syncthreads();
    float v = sm[threadIdx.x][threadIdx.y] * gq[b * DIM + k0 + threadIdx.x];
    size_t o = (size_t)b * DIM * DIM + (size_t)(n0 + threadIdx.y) * DIM + k0 + threadIdx.x;
    th[o] = __float2half_rn(v);
}

// ---------------------------------------------------------------------------
// L2-normalize q and k (fp16 in place). grid = M_TOTAL, 128 thr (4 halfs each).
// ---------------------------------------------------------------------------
__global__ void l2norm_kernel(__half* __restrict__ q, __half* __restrict__ k)
{
    const int row = blockIdx.x;
    const int tid = threadIdx.x;
    __half2* qr = reinterpret_cast<__half2*>(q + (size_t)row * DIM);
    __half2* kr = reinterpret_cast<__half2*>(k + (size_t)row * DIM);

    __half2 q0 = qr[2 * tid], q1 = qr[2 * tid + 1];
    __half2 k0 = kr[2 * tid], k1 = kr[2 * tid + 1];
    float2 qf0 = __half22float2(q0), qf1 = __half22float2(q1);
    float2 kf0 = __half22float2(k0), kf1 = __half22float2(k1);

    float sq = qf0.x * qf0.x + qf0.y * qf0.y + qf1.x * qf1.x + qf1.y * qf1.y;
    float sk = kf0.x * kf0.x + kf0.y * kf0.y + kf1.x * kf1.x + kf1.y * kf1.y;
#pragma unroll
    for (int o = 16; o > 0; o >>= 1) {
        sq += __shfl_xor_sync(0xFFFFFFFFu, sq, o);
        sk += __shfl_xor_sync(0xFFFFFFFFu, sk, o);
    }
    __shared__ float sh[8];
    const int wid = tid >> 5, lane = tid & 31;
    if (lane == 0) { sh[wid] = sq; sh[4 + wid] = sk; }
    __syncthreads();
    sq = sh[0] + sh[1] + sh[2] + sh[3];
    sk = sh[4] + sh[5] + sh[6] + sh[7];
    const float rq = rsqrtf(fmaxf(sq, 1e-12f));
    const float rk = rsqrtf(fmaxf(sk, 1e-12f));

    qr[2 * tid]     = __floats2half2_rn(qf0.x * rq, qf0.y * rq);
    qr[2 * tid + 1] = __floats2half2_rn(qf1.x * rq, qf1.y * rq);
    kr[2 * tid]     = __floats2half2_rn(kf0.x * rk, kf0.y * rk);
    kr[2 * tid + 1] = __floats2half2_rn(kf1.x * rk, kf1.y * rk);
}

__global__ void zero_gq_kernel(float* __restrict__ gq)
{
    int i = blockIdx.x * blockDim.x + threadIdx.x;
    if (i < BATCH * DIM) gq[i] = 0.0f;
}

// gq[b,d] = sum_n qn[b,n,d]  (qn fp16). 128 threads x 4 halfs cover 512 d.
__global__ void batch_sum_kernel(const __half* __restrict__ qn, float* __restrict__ gq)
{
    const int d4 = threadIdx.x;                     // 4-half group 0..127
    const int b  = blockIdx.y;
    const int n0 = blockIdx.z * 256;
    const __half2* base = reinterpret_cast<const __half2*>(
        qn + ((size_t)b * SEQ + n0) * DIM) + 2 * d4;
    float s0 = 0.f, s1 = 0.f, s2 = 0.f, s3 = 0.f;
#pragma unroll 8
    for (int i = 0; i < 256; i++) {
        float2 v0 = __half22float2(base[(size_t)i * (DIM / 2)]);
        float2 v1 = __half22float2(base[(size_t)i * (DIM / 2) + 1]);
        s0 += v0.x; s1 += v0.y; s2 += v1.x; s3 += v1.y;
    }
    float* g = gq + b * DIM + d4 * 4;
    atomicAdd(g + 0, s0);
    atomicAdd(g + 1, s1);
    atomicAdd(g + 2, s2);
    atomicAdd(g + 3, s3);
}

// ---------------------------------------------------------------------------
extern "C" void kernel_launch(void* const* d_in, const int* in_sizes, int n_in,
                              void* d_out, int out_size)
{
    const float* x  = (const float*)d_in[0];
    const float* wq = (const float*)d_in[1];
    const float* bq = (const float*)d_in[2];
    const float* wk = (const float*)d_in[3];
    const float* bk = (const float*)d_in[4];
    const float* wp = (const float*)d_in[5];
    const float* bp = (const float*)d_in[6];
    const float* wf = (const float*)d_in[7];
    const float* bf = (const float*)d_in[8];
    // d_in[9] = w_g: softmax over size-1 axis == 1 -> unused
    float* out = (float*)d_out;

    __half *xh, *qh, *kh, *wT, *wpT;
    float *gq;
    cudaGetSymbolAddress((void**)&xh,  g_xh);
    cudaGetSymbolAddress((void**)&qh,  g_qh);
    cudaGetSymbolAddress((void**)&kh,  g_kh);
    cudaGetSymbolAddress((void**)&wT,  g_wT);
    cudaGetSymbolAddress((void**)&wpT, g_wpT);
    cudaGetSymbolAddress((void**)&gq,  g_gq);

    cudaFuncSetAttribute(mma_gemm<0>, cudaFuncAttributeMaxDynamicSharedMemorySize, GEMM_SMEM);
    cudaFuncSetAttribute(mma_gemm<1>, cudaFuncAttributeMaxDynamicSharedMemorySize, GEMM_SMEM);
    cudaFuncSetAttribute(mma_gemm<2>, cudaFuncAttributeMaxDynamicSharedMemorySize, GEMM_SMEM);

    const int MT = M_TOTAL / 128;            // 256 row tiles
    const size_t NV4 = (size_t)M_TOTAL * DIM / 4;   // float4 count

    // launches 0,1: x -> fp16 (two halves, so GEMM1 is launch #5 for ncu -s 5)
    cvt_x_kernel<<<NV4 / 2 / 256, 256>>>(x, xh, 0);
    cvt_x_kernel<<<NV4 / 2 / 256, 256>>>(x, xh, NV4 / 2);
    // launches 2,3: transpose + convert static weights
    wsplit_kernel<<<dim3(16, 16, 2), dim3(32, 32)>>>(wq, wk, wT, 0);
    wsplit_kernel<<<dim3(16, 16, 1), dim3(32, 32)>>>(wf, wf, wT, 2);
    // launch 4: zero gq accumulator
    zero_gq_kernel<<<(BATCH * DIM + 255) / 256, 256>>>(gq);

    // launch 5 (ncu target): fused q,k GEMM. B rows 0..511 = wq^T, 512..1023 = wk^T
    mma_gemm<0><<<dim3(8, MT), 256, GEMM_SMEM>>>(xh, wT, bq, bk,
                                                 nullptr, nullptr, qh, kh);
    // normalize (fp16 in place)
    l2norm_kernel<<<M_TOTAL, 128>>>(qh, kh);
    // gq = per-batch sum of qn
    batch_sum_kernel<<<dim3(1, BATCH, SEQ / 256), 128>>>(qh, gq);
    // per-batch scaled wp (transposed, fp16)
    wpsplit_kernel<<<dim3(16, 16, BATCH), dim3(32, 32)>>>(wp, gq, wpT);

    // u = kn @ (diag(gq_b) wp) + bp + qn  -> fp16 into xh (x no longer needed)
    mma_gemm<1><<<dim3(4, MT), 256, GEMM_SMEM>>>(kh, wpT, bp, nullptr,
                                                 qh, nullptr, xh, nullptr);
    // out = u @ wf + bf
    mma_gemm<2><<<dim3(4, MT), 256, GEMM_SMEM>>>(xh, wT + 2u * DIM * DIM, bf, nullptr,
                                                 nullptr, out, nullptr, nullptr);
}